// round 3
// baseline (speedup 1.0000x reference)
#include <cuda_runtime.h>
#include <math.h>

// ---------------- problem constants ----------------
#define B_    8
#define R_    10
#define N_    80        // num rois
#define CS    2048
#define CF    256
#define TS    8
#define TF    32
#define KCAT  2304      // CS + CF
#define RD    1024
#define HD    512
#define BINS  49        // 7x7
#define COLSR (N_*BINS) // 3920
#define COLSG (B_*256)  // 2048
#define NC_   60
#define KC9   (HD*9)    // 4608

// ---------------- scratch buffers (device globals; no alloc) ----------------
__device__ float d_fsT[B_ * TS * 256 * CS];   // transposed slow  (134MB)
__device__ float d_ffT[B_ * TF * 256 * CF];   // transposed fast  (67MB)
__device__ float d_rcT[COLSR * KCAT];         // roi concat  [col][k] (36MB)
__device__ float d_gcT[COLSG * KCAT];         // global concat [col][k] (19MB)
__device__ float d_cred[RD * COLSR];          // reduce conv rois  [m][col]
__device__ float d_gfeat[RD * COLSG];         // reduce conv global [m][col]
__device__ float d_roifeats[N_ * RD];
__device__ float d_g1[HD * COLSG];
__device__ float d_a1[N_ * HD];
__device__ float d_x1[N_ * HD * 256];
__device__ float d_x2[N_ * HD * 196];
__device__ float d_x [N_ * HD * BINS];
__device__ float d_q [N_ * HD * BINS];
__device__ float d_k [N_ * HD * BINS];
__device__ float d_v [N_ * HD * BINS];
__device__ float d_virt[N_ * HD * BINS];
__device__ float d_vn  [N_ * HD * BINS];
__device__ float d_att[N_ * R_ * BINS];
__device__ float d_t1[N_ * HD];
__device__ float d_high[N_ * HD];

// ---------------- tiled transpose: [b][c][t][hw] -> [(b*T+t)*256+hw][c] ----------------
__global__ void k_transpose(const float* __restrict__ in, float* __restrict__ outp,
                            int C, int T) {
    __shared__ float tile[32][33];
    int bs = blockIdx.z;
    int b = bs / T, s = bs % T;
    int c0 = blockIdx.x * 32, h0 = blockIdx.y * 32;
    int tx = threadIdx.x, ty = threadIdx.y; // (32, 8)
    #pragma unroll
    for (int i = 0; i < 32; i += 8)
        tile[ty + i][tx] = in[(((size_t)b * C + c0 + ty + i) * T + s) * 256 + h0 + tx];
    __syncthreads();
    #pragma unroll
    for (int i = 0; i < 32; i += 8)
        outp[((size_t)bs * 256 + h0 + ty + i) * C + c0 + tx] = tile[tx][ty + i];
}

// ---------------- ROI align + temporal masked mean (coalesced over c) ----------------
template <int CH>
__global__ void k_roi2(const float* __restrict__ fT, const float* __restrict__ rois,
                       int C, int T, int tstep, int toff, int kbase) {
    int bin = blockIdx.x % BINS;
    int n = blockIdx.x / BINS;
    int t = threadIdx.x; // 256
    int py = bin / 7, px = bin % 7;
    float acc[CH];
    #pragma unroll
    for (int u = 0; u < CH; u++) acc[u] = 0.f;
    int cnt = 0;
    for (int s = 0; s < T; s++) {
        const float* r = rois + (size_t)(n * 32 + toff + s * tstep) * 5;
        float rx1 = r[1], ry1 = r[2], rx2 = r[3], ry2 = r[4];
        if (rx1 == 1.f && ry1 == 1.f && rx2 == 1.f && ry2 == 1.f) continue;
        cnt++;
        int b = (int)r[0];
        float X1 = rx1 * 16.f, Y1 = ry1 * 16.f;
        float rw = fmaxf(rx2 * 16.f - X1, 1.f);
        float rh = fmaxf(ry2 * 16.f - Y1, 1.f);
        float bw = rw * (1.f / 7.f), bh = rh * (1.f / 7.f);
        float gw = ceilf(bw), gh = ceilf(bh);
        float inv = 1.f / (gh * gw);
        const float* base = fT + (size_t)(b * T + s) * 256 * C;
        for (int iy = 0; iy < 3; iy++) {
            if ((float)iy >= gh) break;
            float yy = Y1 + py * bh + (iy + 0.5f) * bh / gh;
            for (int ix = 0; ix < 3; ix++) {
                if ((float)ix >= gw) break;
                float xx = X1 + px * bw + (ix + 0.5f) * bw / gw;
                if (!(yy > -1.f && yy < 16.f && xx > -1.f && xx < 16.f)) continue;
                float y = fminf(fmaxf(yy, 0.f), 15.f);
                float x = fminf(fmaxf(xx, 0.f), 15.f);
                int y0 = (int)floorf(y), x0 = (int)floorf(x);
                int y1 = min(y0 + 1, 15), x1 = min(x0 + 1, 15);
                float ly = y - (float)y0, lx = x - (float)x0;
                float hy = 1.f - ly, hx = 1.f - lx;
                float w00 = hy * hx * inv, w01 = hy * lx * inv;
                float w10 = ly * hx * inv, w11 = ly * lx * inv;
                const float* p00 = base + (size_t)(y0 * 16 + x0) * C;
                const float* p01 = base + (size_t)(y0 * 16 + x1) * C;
                const float* p10 = base + (size_t)(y1 * 16 + x0) * C;
                const float* p11 = base + (size_t)(y1 * 16 + x1) * C;
                #pragma unroll
                for (int u = 0; u < CH; u++) {
                    int c = t + u * 256;
                    acc[u] += w00 * p00[c] + w01 * p01[c] + w10 * p10[c] + w11 * p11[c];
                }
            }
        }
    }
    float invc = 1.f / (float)max(cnt, 1);
    float* o = d_rcT + (size_t)(n * BINS + bin) * KCAT + kbase;
    #pragma unroll
    for (int u = 0; u < CH; u++) o[t + u * 256] = acc[u] * invc;
}

// ---------------- global feature temporal mean -> d_gcT[col][k] ----------------
__global__ void k_gmean2() {
    int idx = blockIdx.x * blockDim.x + threadIdx.x;
    if (idx >= COLSG * KCAT) return;
    int k = idx % KCAT;
    int col = idx / KCAT;
    int b = col >> 8, hw = col & 255;
    float s = 0.f;
    if (k < CS) {
        const float* p = d_fsT + ((size_t)(b * TS) * 256 + hw) * CS + k;
        #pragma unroll
        for (int t = 0; t < TS; t++) s += p[(size_t)t * 256 * CS];
        s *= (1.f / TS);
    } else {
        const float* p = d_ffT + ((size_t)(b * TF) * 256 + hw) * CF + (k - CS);
        #pragma unroll
        for (int t = 0; t < TF; t++) s += p[(size_t)t * 256 * CF];
        s *= (1.f / TF);
    }
    d_gcT[idx] = s;
}

// ---------------- NN SGEMM: C[M,N] = A[M,K] * B[K,N] ----------------
__global__ void k_sgemm(const float* __restrict__ A, int lda,
                        const float* __restrict__ B, int ldb,
                        float* __restrict__ C, int ldc,
                        int M, int N, int K) {
    __shared__ float As[16][65];
    __shared__ float Bs[16][65];
    int m0 = blockIdx.y * 64, n0 = blockIdx.x * 64;
    int t = threadIdx.x;
    int tx = t & 15, ty = t >> 4;
    float acc[4][4];
    #pragma unroll
    for (int i = 0; i < 4; i++)
        #pragma unroll
        for (int j = 0; j < 4; j++) acc[i][j] = 0.f;
    for (int k0 = 0; k0 < K; k0 += 16) {
        #pragma unroll
        for (int i = 0; i < 4; i++) {
            int e = t + i * 256;
            int r = e >> 4, kk = e & 15;
            int gm = m0 + r, gk = k0 + kk;
            As[kk][r] = (gm < M && gk < K) ? A[(size_t)gm * lda + gk] : 0.f;
        }
        #pragma unroll
        for (int i = 0; i < 4; i++) {
            int e = t + i * 256;
            int kk = e >> 6, cc = e & 63;
            int gk = k0 + kk, gn = n0 + cc;
            Bs[kk][cc] = (gk < K && gn < N) ? B[(size_t)gk * ldb + gn] : 0.f;
        }
        __syncthreads();
        #pragma unroll
        for (int kk = 0; kk < 16; kk++) {
            float a[4], b[4];
            #pragma unroll
            for (int i = 0; i < 4; i++) { a[i] = As[kk][ty * 4 + i]; b[i] = Bs[kk][tx * 4 + i]; }
            #pragma unroll
            for (int i = 0; i < 4; i++)
                #pragma unroll
                for (int j = 0; j < 4; j++) acc[i][j] += a[i] * b[j];
        }
        __syncthreads();
    }
    #pragma unroll
    for (int i = 0; i < 4; i++) {
        int gm = m0 + ty * 4 + i;
        if (gm >= M) continue;
        #pragma unroll
        for (int j = 0; j < 4; j++) {
            int gn = n0 + tx * 4 + j;
            if (gn < N) C[(size_t)gm * ldc + gn] = acc[i][j];
        }
    }
}

// ---------------- NT SGEMM: C[M,N] = A[M,K] * B[N,K]^T (both k-contiguous) ----------------
__global__ void k_sgemm_nt(const float* __restrict__ A, int lda,
                           const float* __restrict__ B, int ldb,
                           float* __restrict__ C, int ldc,
                           int M, int N, int K) {
    __shared__ float As[16][65];
    __shared__ float Bs[16][65];
    int m0 = blockIdx.y * 64, n0 = blockIdx.x * 64;
    int t = threadIdx.x;
    int tx = t & 15, ty = t >> 4;
    float acc[4][4];
    #pragma unroll
    for (int i = 0; i < 4; i++)
        #pragma unroll
        for (int j = 0; j < 4; j++) acc[i][j] = 0.f;
    for (int k0 = 0; k0 < K; k0 += 16) {
        #pragma unroll
        for (int i = 0; i < 4; i++) {
            int e = t + i * 256;
            int r = e >> 4, kk = e & 15;
            int gm = m0 + r, gk = k0 + kk;
            As[kk][r] = (gm < M && gk < K) ? A[(size_t)gm * lda + gk] : 0.f;
        }
        #pragma unroll
        for (int i = 0; i < 4; i++) {
            int e = t + i * 256;
            int r = e >> 4, kk = e & 15;
            int gn = n0 + r, gk = k0 + kk;
            Bs[kk][r] = (gn < N && gk < K) ? B[(size_t)gn * ldb + gk] : 0.f;
        }
        __syncthreads();
        #pragma unroll
        for (int kk = 0; kk < 16; kk++) {
            float a[4], b[4];
            #pragma unroll
            for (int i = 0; i < 4; i++) { a[i] = As[kk][ty * 4 + i]; b[i] = Bs[kk][tx * 4 + i]; }
            #pragma unroll
            for (int i = 0; i < 4; i++)
                #pragma unroll
                for (int j = 0; j < 4; j++) acc[i][j] += a[i] * b[j];
        }
        __syncthreads();
    }
    #pragma unroll
    for (int i = 0; i < 4; i++) {
        int gm = m0 + ty * 4 + i;
        if (gm >= M) continue;
        #pragma unroll
        for (int j = 0; j < 4; j++) {
            int gn = n0 + tx * 4 + j;
            if (gn < N) C[(size_t)gm * ldc + gn] = acc[i][j];
        }
    }
}

// ---------------- max over 49 bins -> roi_feats ----------------
__global__ void k_maxbins() {
    int idx = blockIdx.x * blockDim.x + threadIdx.x;
    if (idx >= N_ * RD) return;
    int n = idx / RD, m = idx % RD;
    const float* p = d_cred + (size_t)m * COLSR + n * BINS;
    float mx = p[0];
    #pragma unroll
    for (int j = 1; j < BINS; j++) mx = fmaxf(mx, p[j]);
    d_roifeats[n * RD + m] = mx;
}

// ---------------- actor part of conv1 ----------------
__global__ void k_a1(const float* __restrict__ w1) {
    int idx = blockIdx.x * blockDim.x + threadIdx.x;
    if (idx >= N_ * HD) return;
    int n = idx / HD, m = idx % HD;
    const float* w = w1 + (size_t)m * 2048 + 1024;
    const float* rf = d_roifeats + n * RD;
    float s = 0.f;
    for (int k = 0; k < RD; k++) s += w[k] * rf[k];
    d_a1[idx] = s;
}

// ---------------- x1 = relu(g1[b] + a1 broadcast) ----------------
__global__ void k_combine() {
    int idx = blockIdx.x * blockDim.x + threadIdx.x;
    if (idx >= N_ * HD * 256) return;
    int p = idx & 255;
    int m = (idx >> 8) % HD;
    int n = idx / (HD * 256);
    int b = n / R_;
    float v = d_g1[(size_t)m * COLSG + b * 256 + p] + d_a1[n * HD + m];
    d_x1[idx] = fmaxf(v, 0.f);
}

// ---------------- conv2 as im2col-GEMM: 16x16 -> 14x14 valid, relu ----------------
// C[m, col] = sum_k W[m][k] * B(k,col);  k = c*9+tap, col = n*196+q
__global__ void k_cgemm16(const float* __restrict__ W, const float* __restrict__ X,
                          float* __restrict__ out) {
    __shared__ float As[16][65];
    __shared__ float Bs[16][65];
    const int NTOT = N_ * 196;
    int m0 = blockIdx.y * 64, c0 = blockIdx.x * 64;
    int t = threadIdx.x;
    int tx = t & 15, ty = t >> 4;
    // per-thread fixed im2col coords for B loads
    int ccf = t & 63;
    int colf = c0 + ccf;
    int nf = colf / 196, qf = colf % 196;
    int oyf = qf / 14, oxf = qf % 14;
    float acc[4][4];
    #pragma unroll
    for (int i = 0; i < 4; i++)
        #pragma unroll
        for (int j = 0; j < 4; j++) acc[i][j] = 0.f;
    for (int k0 = 0; k0 < KC9; k0 += 16) {
        #pragma unroll
        for (int i = 0; i < 4; i++) {
            int r = (t >> 4) + i * 16, kk = t & 15;
            As[kk][r] = W[(size_t)(m0 + r) * KC9 + k0 + kk];
        }
        #pragma unroll
        for (int i = 0; i < 4; i++) {
            int kk = (t >> 6) + i * 4;
            int k = k0 + kk;
            int c = k / 9, tap = k - c * 9;
            int iy = oyf + tap / 3, ix = oxf + tap % 3;
            float v = 0.f;
            if (colf < NTOT)
                v = X[(size_t)nf * (HD * 256) + c * 256 + iy * 16 + ix];
            Bs[kk][ccf] = v;
        }
        __syncthreads();
        #pragma unroll
        for (int kk = 0; kk < 16; kk++) {
            float a[4], b[4];
            #pragma unroll
            for (int i = 0; i < 4; i++) { a[i] = As[kk][ty * 4 + i]; b[i] = Bs[kk][tx * 4 + i]; }
            #pragma unroll
            for (int i = 0; i < 4; i++)
                #pragma unroll
                for (int j = 0; j < 4; j++) acc[i][j] += a[i] * b[j];
        }
        __syncthreads();
    }
    #pragma unroll
    for (int i = 0; i < 4; i++) {
        int m = m0 + ty * 4 + i;
        #pragma unroll
        for (int j = 0; j < 4; j++) {
            int col = c0 + tx * 4 + j;
            if (col < NTOT) {
                int n = col / 196, q = col % 196;
                out[(size_t)n * (HD * 196) + (size_t)m * 196 + q] = fmaxf(acc[i][j], 0.f);
            }
        }
    }
}

// ---------------- HR2O 3x3 pad-1 conv on 7x7 as im2col-GEMM ----------------
// col = n*49+p ; optional accumulate
__global__ void k_cgemm7(const float* __restrict__ W, const float* __restrict__ X,
                         float* __restrict__ out, int accumulate) {
    __shared__ float As[16][65];
    __shared__ float Bs[16][65];
    int m0 = blockIdx.y * 64, c0 = blockIdx.x * 64;
    int t = threadIdx.x;
    int tx = t & 15, ty = t >> 4;
    int ccf = t & 63;
    int colf = c0 + ccf;
    int nf = colf / BINS, pf = colf % BINS;
    int pyf = pf / 7, pxf = pf % 7;
    float acc[4][4];
    #pragma unroll
    for (int i = 0; i < 4; i++)
        #pragma unroll
        for (int j = 0; j < 4; j++) acc[i][j] = 0.f;
    for (int k0 = 0; k0 < KC9; k0 += 16) {
        #pragma unroll
        for (int i = 0; i < 4; i++) {
            int r = (t >> 4) + i * 16, kk = t & 15;
            As[kk][r] = W[(size_t)(m0 + r) * KC9 + k0 + kk];
        }
        #pragma unroll
        for (int i = 0; i < 4; i++) {
            int kk = (t >> 6) + i * 4;
            int k = k0 + kk;
            int c = k / 9, tap = k - c * 9;
            int iy = pyf + tap / 3 - 1, ix = pxf + tap % 3 - 1;
            float v = 0.f;
            if (colf < COLSR && (unsigned)iy < 7u && (unsigned)ix < 7u)
                v = X[(size_t)nf * (HD * BINS) + c * BINS + iy * 7 + ix];
            Bs[kk][ccf] = v;
        }
        __syncthreads();
        #pragma unroll
        for (int kk = 0; kk < 16; kk++) {
            float a[4], b[4];
            #pragma unroll
            for (int i = 0; i < 4; i++) { a[i] = As[kk][ty * 4 + i]; b[i] = Bs[kk][tx * 4 + i]; }
            #pragma unroll
            for (int i = 0; i < 4; i++)
                #pragma unroll
                for (int j = 0; j < 4; j++) acc[i][j] += a[i] * b[j];
        }
        __syncthreads();
    }
    #pragma unroll
    for (int i = 0; i < 4; i++) {
        int m = m0 + ty * 4 + i;
        #pragma unroll
        for (int j = 0; j < 4; j++) {
            int col = c0 + tx * 4 + j;
            if (col < COLSR) {
                int n = col / BINS, p = col % BINS;
                size_t o = (size_t)n * (HD * BINS) + (size_t)m * BINS + p;
                if (accumulate) out[o] += acc[i][j];
                else out[o] = acc[i][j];
            }
        }
    }
}

// ---------------- maxpool 3x3/s2/p1 : 14x14 -> 7x7 ----------------
__global__ void k_pool() {
    int idx = blockIdx.x * blockDim.x + threadIdx.x;
    if (idx >= N_ * HD * BINS) return;
    int q = idx % BINS;
    int nm = idx / BINS;
    int oy = q / 7, ox = q % 7;
    int y0 = max(0, 2 * oy - 1), y1 = min(13, 2 * oy + 1);
    int x0 = max(0, 2 * ox - 1), x1 = min(13, 2 * ox + 1);
    const float* p = d_x2 + (size_t)nm * 196;
    float mx = -1e30f;
    for (int y = y0; y <= y1; y++)
        for (int x = x0; x <= x1; x++) mx = fmaxf(mx, p[y * 14 + x]);
    d_x[idx] = mx;
}

// ---------------- attention: per (b, pixel) 10x10 + softmax over j ----------------
__global__ void k_att() {
    int p = blockIdx.x;   // 0..48
    int b = blockIdx.y;   // 0..7
    __shared__ float sq[R_ * HD];
    __shared__ float sk[R_ * HD];
    __shared__ float sa[R_][R_];
    int t = threadIdx.x;  // 128
    for (int e = t; e < R_ * HD; e += 128) {
        int i = e >> 9;
        int c = e & 511;
        size_t base = ((size_t)(b * R_ + i) * HD + c) * BINS + p;
        sq[e] = d_q[base];
        sk[e] = d_k[base];
    }
    __syncthreads();
    if (t < R_ * R_) {
        int i = t / R_, j = t % R_;
        float s = 0.f;
        const float* qi = &sq[i * HD];
        const float* kj = &sk[j * HD];
        for (int c = 0; c < HD; c++) s += qi[c] * kj[c];
        sa[i][j] = s * 0.04419417382415922f; // 1/sqrt(512)
    }
    __syncthreads();
    if (t < R_) {
        int i = t;
        float mx = sa[i][0];
        #pragma unroll
        for (int j = 1; j < R_; j++) mx = fmaxf(mx, sa[i][j]);
        float e[R_], sum = 0.f;
        #pragma unroll
        for (int j = 0; j < R_; j++) { e[j] = expf(sa[i][j] - mx); sum += e[j]; }
        float inv = 1.f / sum;
        #pragma unroll
        for (int j = 0; j < R_; j++)
            d_att[((size_t)(b * R_ + i) * R_ + j) * BINS + p] = e[j] * inv;
    }
}

// ---------------- virt = att x v ----------------
__global__ void k_virt() {
    int idx = blockIdx.x * blockDim.x + threadIdx.x;
    if (idx >= N_ * HD * BINS) return;
    int p = idx % BINS;
    int c = (idx / BINS) % HD;
    int n = idx / (BINS * HD);
    int b = n / R_, i = n % R_;
    float s = 0.f;
    #pragma unroll
    for (int j = 0; j < R_; j++) {
        float a = d_att[((size_t)(b * R_ + i) * R_ + j) * BINS + p];
        float vv = d_v[((size_t)(b * R_ + j) * HD + c) * BINS + p];
        s += a * vv;
    }
    d_virt[idx] = s;
}

// ---------------- per-sample layernorm + affine + relu ----------------
__global__ void k_norm(const float* __restrict__ g, const float* __restrict__ bb) {
    int n = blockIdx.x;
    int t = threadIdx.x;
    const int CNT = HD * BINS; // 25088
    const float* vp = d_virt + (size_t)n * CNT;
    float s = 0.f, ss = 0.f;
    for (int e = t; e < CNT; e += 256) {
        float x = vp[e];
        s += x; ss += x * x;
    }
    __shared__ float rs[8], rss[8];
    #pragma unroll
    for (int o = 16; o > 0; o >>= 1) {
        s += __shfl_down_sync(0xffffffffu, s, o);
        ss += __shfl_down_sync(0xffffffffu, ss, o);
    }
    if ((t & 31) == 0) { rs[t >> 5] = s; rss[t >> 5] = ss; }
    __syncthreads();
    __shared__ float smu, srstd;
    if (t == 0) {
        float S = 0.f, SS = 0.f;
        #pragma unroll
        for (int i = 0; i < 8; i++) { S += rs[i]; SS += rss[i]; }
        float mu = S / (float)CNT;
        float var = SS / (float)CNT - mu * mu;
        smu = mu;
        srstd = rsqrtf(var + 1e-5f);
    }
    __syncthreads();
    float mu = smu, rstd = srstd;
    float* op = d_vn + (size_t)n * CNT;
    for (int e = t; e < CNT; e += 256) {
        int c = e / BINS;
        float v = (vp[e] - mu) * rstd * g[c] + bb[c];
        op[e] = fmaxf(v, 0.f);
    }
}

// ---------------- high_order mean, fc1, final out ----------------
__global__ void k_high() {
    int idx = blockIdx.x * blockDim.x + threadIdx.x;
    if (idx >= N_ * HD) return;
    const float* p = d_x + (size_t)idx * BINS;
    float s = 0.f;
    #pragma unroll
    for (int j = 0; j < BINS; j++) s += p[j];
    d_high[idx] = s * (1.f / BINS);
}

__global__ void k_fc1(const float* __restrict__ fc1) {
    int idx = blockIdx.x * blockDim.x + threadIdx.x;
    if (idx >= N_ * HD) return;
    int n = idx / HD, h = idx % HD;
    const float* rf = d_roifeats + n * RD;
    const float* w = fc1 + (size_t)h * RD;
    float s = 0.f;
    for (int k = 0; k < RD; k++) s += rf[k] * w[k];
    d_t1[idx] = fmaxf(s, 0.f);
}

__global__ void k_out(const float* __restrict__ fc2, float* __restrict__ out) {
    int idx = blockIdx.x * blockDim.x + threadIdx.x;
    if (idx >= N_ * NC_) return;
    int n = idx / NC_, o = idx % NC_;
    const float* w = fc2 + (size_t)o * 1024;
    const float* a = d_t1 + n * HD;
    const float* h = d_high + n * HD;
    float s = 0.f;
    for (int k = 0; k < HD; k++) s += a[k] * w[k];
    for (int k = 0; k < HD; k++) s += h[k] * w[512 + k];
    out[idx] = s;
}

// ---------------- host launch ----------------
static float* sym(const void* s) {
    void* p = nullptr;
    cudaGetSymbolAddress(&p, s);
    return (float*)p;
}

extern "C" void kernel_launch(void* const* d_in, const int* in_sizes, int n_in,
                              void* d_out, int out_size) {
    const float* feat_slow = (const float*)d_in[0];
    const float* feat_fast = (const float*)d_in[1];
    const float* rois      = (const float*)d_in[2];
    int wb = n_in - 11; // weights start (robust to scalar inputs present or not)
    const float* w_reduce = (const float*)d_in[wb + 0];
    const float* w_conv1  = (const float*)d_in[wb + 1];
    const float* w_conv2  = (const float*)d_in[wb + 2];
    const float* wq       = (const float*)d_in[wb + 3];
    const float* wk       = (const float*)d_in[wb + 4];
    const float* wv       = (const float*)d_in[wb + 5];
    const float* wm       = (const float*)d_in[wb + 6];
    const float* gn_g     = (const float*)d_in[wb + 7];
    const float* gn_b     = (const float*)d_in[wb + 8];
    const float* fc1_w    = (const float*)d_in[wb + 9];
    const float* fc2_w    = (const float*)d_in[wb + 10];
    float* out = (float*)d_out;

    float* p_fsT   = sym(d_fsT);
    float* p_ffT   = sym(d_ffT);
    float* p_rcT   = sym(d_rcT);
    float* p_gcT   = sym(d_gcT);
    float* p_cred  = sym(d_cred);
    float* p_gfeat = sym(d_gfeat);
    float* p_g1    = sym(d_g1);
    float* p_x1    = sym(d_x1);
    float* p_x2    = sym(d_x2);
    float* p_x     = sym(d_x);
    float* p_q     = sym(d_q);
    float* p_k     = sym(d_k);
    float* p_v     = sym(d_v);
    float* p_vn    = sym(d_vn);

    // 0) transpose features to channel-last
    k_transpose<<<dim3(CS / 32, 8, B_ * TS), dim3(32, 8)>>>(feat_slow, p_fsT, CS, TS);
    k_transpose<<<dim3(CF / 32, 8, B_ * TF), dim3(32, 8)>>>(feat_fast, p_ffT, CF, TF);
    // 1) ROI align (slow uses rois[:, 3::4], fast uses all 32)
    k_roi2<8><<<N_ * BINS, 256>>>(p_fsT, rois, CS, TS, 4, 3, 0);
    k_roi2<1><<<N_ * BINS, 256>>>(p_ffT, rois, CF, TF, 1, 0, CS);
    // 2) global temporal mean
    k_gmean2<<<(COLSG * KCAT + 255) / 256, 256>>>();
    // 3) reduce conv (1x1): NT gemms
    k_sgemm_nt<<<dim3((COLSR + 63) / 64, RD / 64), 256>>>(
        w_reduce, KCAT, p_rcT, KCAT, p_cred, COLSR, RD, COLSR, KCAT);
    k_sgemm_nt<<<dim3(COLSG / 64, RD / 64), 256>>>(
        w_reduce, KCAT, p_gcT, KCAT, p_gfeat, COLSG, RD, COLSG, KCAT);
    // 4) spatial max -> roi_feats
    k_maxbins<<<(N_ * RD + 255) / 256, 256>>>();
    // 5) conv1 split
    k_sgemm<<<dim3(COLSG / 64, HD / 64), 256>>>(
        w_conv1, 2048, p_gfeat, COLSG, p_g1, COLSG, HD, COLSG, RD);
    k_a1<<<(N_ * HD + 255) / 256, 256>>>(w_conv1);
    k_combine<<<(N_ * HD * 256 + 255) / 256, 256>>>();
    // 6) conv2 3x3 valid + relu (im2col gemm)
    k_cgemm16<<<dim3(N_ * 196 / 64, HD / 64), 256>>>(w_conv2, p_x1, p_x2);
    // 7) maxpool -> 7x7
    k_pool<<<(N_ * HD * BINS + 255) / 256, 256>>>();
    // 8) HR2O x D
    for (int d = 0; d < 2; d++) {
        const float* wq_d = wq + (size_t)d * HD * KC9;
        const float* wk_d = wk + (size_t)d * HD * KC9;
        const float* wv_d = wv + (size_t)d * HD * KC9;
        const float* wm_d = wm + (size_t)d * HD * KC9;
        dim3 g7((COLSR + 63) / 64, HD / 64);
        k_cgemm7<<<g7, 256>>>(wq_d, p_x, p_q, 0);
        k_cgemm7<<<g7, 256>>>(wk_d, p_x, p_k, 0);
        k_cgemm7<<<g7, 256>>>(wv_d, p_x, p_v, 0);
        k_att<<<dim3(BINS, B_), 128>>>();
        k_virt<<<(N_ * HD * BINS + 255) / 256, 256>>>();
        k_norm<<<N_, 256>>>(gn_g + d * HD, gn_b + d * HD);
        k_cgemm7<<<g7, 256>>>(wm_d, p_vn, p_x, 1); // x += conv(relu(norm))
    }
    // 9) heads
    k_high<<<(N_ * HD + 255) / 256, 256>>>();
    k_fc1<<<(N_ * HD + 255) / 256, 256>>>(fc1_w);
    k_out<<<(N_ * NC_ + 255) / 256, 256>>>(fc2_w, out);
    (void)in_sizes; (void)out_size;
}